// round 2
// baseline (speedup 1.0000x reference)
#include <cuda_runtime.h>

// SplineActivation: y[b,w] = clamped cubic B-spline (16 uniform knots on [-3,3],
// degree 3) of x[b,w] with per-channel coefficients coefs[w, 0..17].
//
// Round-2 strategy: the clamped spline is C^2 (simple interior knots), so it has
// an exact *uniform* cubic B-spline representation on the 15-interval grid:
// 18 effective control points P[c][i] per channel with
//     y = sum_j U_j(u) * P[c][k+j],   u = (x - knot_k)/h  in [0,1],
// where U_j are the FIXED uniform segment basis cubics (compile-time consts).
// Hot kernel: interval index -> 4 conflict-free scalar LDS -> ~14 FMA.
// 36KB smem tile (vs 61KB for per-interval cubics) -> 32 warps/SM, and float2
// global I/O with 4-row unroll -> 32B/thread of LDG in flight.

#define W_TOTAL   1024
#define B_TOTAL   8192
#define CH_TILE   512          // channels per block (256 threads x float2)
#define BD        256
#define R_UNROLL  4
#define N_CTRL    18

// 72 KB static device scratch: effective control points, layout [i][channel].
__device__ float g_P[N_CTRL * W_TOTAL];

// ---------------------------------------------------------------------------
// Build: one thread per (channel, control point). Fit the interval cubic in u
// (FP64 Cox-de Boor sampled at 4 points, Newton divided differences), then the
// control point via the polar form (blossom) at integer knot args (j-2,j-1,j).
// ---------------------------------------------------------------------------
__global__ void build_ctrl_kernel(const float* __restrict__ coefs) {
    int idx = blockIdx.x * blockDim.x + threadIdx.x;
    if (idx >= N_CTRL * W_TOTAL) return;
    int c = idx & (W_TOTAL - 1);
    int i = idx >> 10;                       // control point 0..17

    // Clamped knot vector t[0..21] (float32 knots promoted to double)
    double t[22];
#pragma unroll
    for (int j = 0; j < 16; j++) {
        double kd = -3.0 + (double)j * (6.0 / 15.0);
        t[3 + j] = (double)(float)kd;
    }
    t[0] = t[1] = t[2] = t[3];
    t[19] = t[20] = t[21] = t[18];

    // Pick an interval containing this control point's support: k<=i<=k+3.
    int k = i - 2; if (k < 0) k = 0; if (k > 14) k = 14;
    int kg = k + 3;

    double cf[4];
#pragma unroll
    for (int j = 0; j < 4; j++) cf[j] = (double)coefs[c * N_CTRL + k + j];

    const double x0    = t[kg];
    const double delta = (t[kg + 1] - t[kg]) / 3.0;
    // Match the hot kernel's interval origin exactly:
    const double K = (double)fmaf((float)k, 0.4f, -3.0f);

    double uu[4], ff[4];
#pragma unroll
    for (int m = 0; m < 4; m++) {
        double x = x0 + delta * (double)m;
        uu[m] = (x - K) * 2.5;
        double left[3], right[3];
#pragma unroll
        for (int i2 = 1; i2 <= 3; i2++) {
            left [i2 - 1] = x - t[kg + 1 - i2];
            right[i2 - 1] = t[kg + i2] - x;
        }
        double N[4];
        N[0] = 1.0;
#pragma unroll
        for (int j = 1; j <= 3; j++) {
            double saved = 0.0;
#pragma unroll
            for (int r = 0; r < j; r++) {
                double temp = N[r] / (right[r] + left[j - 1 - r]);
                N[r] = saved + right[r] * temp;
                saved = left[j - 1 - r] * temp;
            }
            N[j] = saved;
        }
        ff[m] = N[0]*cf[0] + N[1]*cf[1] + N[2]*cf[2] + N[3]*cf[3];
    }

    // Newton divided differences in u -> monomial coeffs b0..b3.
    double d1[3], d2[2], d3;
#pragma unroll
    for (int m = 0; m < 3; m++) d1[m] = (ff[m+1] - ff[m]) / (uu[m+1] - uu[m]);
#pragma unroll
    for (int m = 0; m < 2; m++) d2[m] = (d1[m+1] - d1[m]) / (uu[m+2] - uu[m]);
    d3 = (d2[1] - d2[0]) / (uu[3] - uu[0]);

    // Expand Newton form: p = n0 + n1(u-u0) + n2(u-u0)(u-u1) + n3(u-u0)(u-u1)(u-u2)
    double b0 = d3, b1 = 0.0, b2 = 0.0, b3 = 0.0;  // working poly, degree grows
    // multiply by (u - u2), add d2[0]:
    { double nb3 = 0.0, nb2 = b0;  // current poly is degree 0 = d3
      double p0 = d3;
      // poly = d3*(u-u2) + d2[0]
      b1 = p0; b0 = d2[0] - p0 * uu[2];
      // poly = (b1 u + b0)*(u - u1) + d1[0]
      b2 = b1; b1 = b0 - b1 * uu[1]; b0 = d1[0] - b0 * uu[1];
      // poly = (b2 u^2 + b1 u + b0)*(u - u0) + f0
      b3 = b2; b2 = b1 - b2 * uu[0]; b1 = b0 - b1 * uu[0]; b0 = ff[0] - b0 * uu[0];
      (void)nb3; (void)nb2;
    }

    // Blossom at integer args (j-2, j-1, j), j = i - k:
    // F(a,b,c) = b0 + b1*(a+b+c)/3 + b2*(ab+ac+bc)/3 + b3*abc
    double ja = (double)(i - k) - 2.0, jb = ja + 1.0, jc = ja + 2.0;
    double e1 = ja + jb + jc;
    double e2 = ja*jb + ja*jc + jb*jc;
    double e3 = ja*jb*jc;
    double P = b0 + b1 * e1 * (1.0/3.0) + b2 * e2 * (1.0/3.0) + b3 * e3;

    g_P[i * W_TOTAL + c] = (float)P;
}

// ---------------------------------------------------------------------------
// Hot kernel. 256 threads; thread t owns channel pair (c0+2t, c0+2t+1).
// smem layout sp[e][i][256]: bank = lane id -> conflict-free for any k.
// ---------------------------------------------------------------------------
__device__ __forceinline__ float eval_one(float x, const float* __restrict__ tab) {
    float u0 = fmaf(x, 2.5f, 7.5f);
    float fi = fminf(fmaxf(floorf(u0), 0.0f), 14.0f);
    int   k  = (int)fi;
    float u  = (x - fmaf(fi, 0.4f, -3.0f)) * 2.5f;

    float v  = 1.0f - u;
    float U0 = v * v * v * (1.0f / 6.0f);
    float uu = u * u;
    float U3 = uu * u * (1.0f / 6.0f);
    float w  = fmaf(-0.5f, u, 0.5f);
    w        = fmaf(w, u, 0.5f);
    float U2 = fmaf(w * u, 1.0f, 1.0f / 6.0f);   // ((-u/2+1/2)u+1/2)u + 1/6
    float U1 = 1.0f - U0 - U2 - U3;

    const float* p = tab + k * BD;
    float y = U0 * p[0];
    y = fmaf(U1, p[BD],     y);
    y = fmaf(U2, p[2 * BD], y);
    y = fmaf(U3, p[3 * BD], y);
    return y;
}

__global__ __launch_bounds__(BD, 4)
void spline_eval_kernel(const float* __restrict__ X, float* __restrict__ Y) {
    __shared__ float sp[2][N_CTRL][BD];   // 36,864 B
    const int t  = threadIdx.x;
    const int c0 = blockIdx.x * CH_TILE;

#pragma unroll
    for (int i = 0; i < N_CTRL; i++) {
        float2 v = *(const float2*)&g_P[i * W_TOTAL + c0 + 2 * t];
        sp[0][i][t] = v.x;
        sp[1][i][t] = v.y;
    }
    __syncthreads();

    const float* tab0 = &sp[0][0][0] + t;
    const float* tab1 = &sp[1][0][0] + t;

    const int pair0 = (c0 >> 1) + t;            // float2 column index
    const int rstep = gridDim.y * R_UNROLL;

    for (int r0 = blockIdx.y * R_UNROLL; r0 < B_TOTAL; r0 += rstep) {
        const float2* xp = (const float2*)X + (size_t)r0 * (W_TOTAL / 2) + pair0;
        float2*       yp = (float2*)Y       + (size_t)r0 * (W_TOTAL / 2) + pair0;

        float2 xv[R_UNROLL];
#pragma unroll
        for (int q = 0; q < R_UNROLL; q++) xv[q] = xp[q * (W_TOTAL / 2)];

        float2 rv[R_UNROLL];
#pragma unroll
        for (int q = 0; q < R_UNROLL; q++) {
            rv[q].x = eval_one(xv[q].x, tab0);
            rv[q].y = eval_one(xv[q].y, tab1);
        }
#pragma unroll
        for (int q = 0; q < R_UNROLL; q++) yp[q * (W_TOTAL / 2)] = rv[q];
    }
}

// ---------------------------------------------------------------------------
extern "C" void kernel_launch(void* const* d_in, const int* in_sizes, int n_in,
                              void* d_out, int out_size) {
    const float* X     = (const float*)d_in[0];
    const float* coefs = (const float*)d_in[1];
    if (n_in >= 2 && in_sizes[0] < in_sizes[1]) {   // identify by size
        X     = (const float*)d_in[1];
        coefs = (const float*)d_in[0];
    }
    float* Y = (float*)d_out;

    build_ctrl_kernel<<<(N_CTRL * W_TOTAL + 255) / 256, 256>>>(coefs);

    dim3 grid(W_TOTAL / CH_TILE, 296);   // 2 x 296 = 592 = 4 per SM x 148
    spline_eval_kernel<<<grid, BD>>>(X, Y);
}

// round 3
// speedup vs baseline: 1.0780x; 1.0780x over previous
#include <cuda_runtime.h>

// SplineActivation: y[b,w] = clamped cubic B-spline (16 uniform knots on [-3,3],
// degree 3) of x[b,w], per-channel coefficients coefs[w, 0..17].
//
// Round-3 strategy:
//  * Hot kernel = round-1 math (per-(interval,channel) monomial cubic float4,
//    1 conflict-free LDS.128 + 3-FMA Horner per element) but with a 128-channel
//    tile -> 30KB smem -> 6 CTAs/SM (48 warps), grid 8x111 = 888 = one exact wave.
//  * Build split into (A) FP64 computation of the fixed 15x(4x4) interval
//    conversion matrices (60 threads, negligible) and (B) FP32 application to
//    all channels (16 FMAs per table entry). Kills the FP64 build overhead.

#define W_TOTAL  1024
#define B_TOTAL  8192
#define NB_IV    15
#define CH       128
#define BD       256
#define N_CTRL   18

// Static device scratch (no allocation APIs).
__device__ float4 g_M[NB_IV * 4];            // [interval][j] -> (a0,a1,a2,a3)
__device__ float4 g_poly[NB_IV * W_TOTAL];   // [interval][channel] monomial cubic

// ---------------------------------------------------------------------------
// Kernel A: 60 threads. Entry (k, j): monomial cubic (in s = x - K_eval(k)) of
// basis function N_{k+j} restricted to interval k, via FP64 Cox-de Boor sampled
// at 4 points + uniform divided differences + shift to the eval-kernel origin.
// ---------------------------------------------------------------------------
__global__ void build_matrix_kernel() {
    int idx = blockIdx.x * blockDim.x + threadIdx.x;
    if (idx >= NB_IV * 4) return;
    int k = idx >> 2;            // interval 0..14
    int j = idx & 3;             // local coef index 0..3

    // Clamped knot vector t[0..21] (float32 knots promoted to double)
    double t[22];
#pragma unroll
    for (int m = 0; m < 16; m++) {
        double kd = -3.0 + (double)m * (6.0 / 15.0);
        t[3 + m] = (double)(float)kd;
    }
    t[0] = t[1] = t[2] = t[3];
    t[19] = t[20] = t[21] = t[18];

    const int kg = k + 3;
    const double x0    = t[kg];
    const double delta = (t[kg + 1] - t[kg]) / 3.0;
    const double Kev   = (double)fmaf((float)k, 0.4f, -3.0f); // eval origin (fp32 fma)

    double f[4];
#pragma unroll
    for (int m = 0; m < 4; m++) {
        double x = x0 + delta * (double)m;
        double left[3], right[3];
#pragma unroll
        for (int i2 = 1; i2 <= 3; i2++) {
            left [i2 - 1] = x - t[kg + 1 - i2];
            right[i2 - 1] = t[kg + i2] - x;
        }
        double N[4];
        N[0] = 1.0;
#pragma unroll
        for (int jj = 1; jj <= 3; jj++) {
            double saved = 0.0;
#pragma unroll
            for (int r = 0; r < jj; r++) {
                double temp = N[r] / (right[r] + left[jj - 1 - r]);
                N[r] = saved + right[r] * temp;
                saved = left[jj - 1 - r] * temp;
            }
            N[jj] = saved;
        }
        f[m] = N[j];            // unit coefficient e_j
    }

    // Uniform divided differences -> poly in w = x - x0.
    double d1 = (f[1] - f[0]) / delta;
    double d2 = (f[2] - 2.0 * f[1] + f[0]) / (2.0 * delta * delta);
    double d3 = (f[3] - 3.0 * f[2] + 3.0 * f[1] - f[0]) / (6.0 * delta * delta * delta);
    double a0 = f[0];
    double a1 = d1 - delta * d2 + 2.0 * delta * delta * d3;
    double a2 = d2 - 3.0 * delta * d3;
    double a3 = d3;

    // Shift to s = x - Kev:  w = s - s0,  s0 = x0 - Kev (tiny).
    double s0 = x0 - Kev;
    double b3 = a3;
    double b2 = a2 - 3.0 * a3 * s0;
    double b1 = a1 - 2.0 * a2 * s0 + 3.0 * a3 * s0 * s0;
    double b0 = a0 - a1 * s0 + a2 * s0 * s0 - a3 * s0 * s0 * s0;

    g_M[k * 4 + j] = make_float4((float)b0, (float)b1, (float)b2, (float)b3);
}

// ---------------------------------------------------------------------------
// Kernel B: apply the conversion matrices to all channels. 15360 threads,
// 16 FP32 FMAs each.
// ---------------------------------------------------------------------------
__global__ void apply_matrix_kernel(const float* __restrict__ coefs) {
    int idx = blockIdx.x * blockDim.x + threadIdx.x;
    if (idx >= NB_IV * W_TOTAL) return;
    int c = idx & (W_TOTAL - 1);
    int k = idx >> 10;

    float4 acc = make_float4(0.f, 0.f, 0.f, 0.f);
#pragma unroll
    for (int j = 0; j < 4; j++) {
        float  cf = coefs[c * N_CTRL + k + j];
        float4 m  = g_M[k * 4 + j];
        acc.x = fmaf(cf, m.x, acc.x);
        acc.y = fmaf(cf, m.y, acc.y);
        acc.z = fmaf(cf, m.z, acc.z);
        acc.w = fmaf(cf, m.w, acc.w);
    }
    g_poly[k * W_TOTAL + c] = acc;
}

// ---------------------------------------------------------------------------
// Hot kernel. Block = 256 threads over a 128-channel tile: ch = t&127,
// rl = t>>7 selects a row sub-group; each iteration covers 8 rows per block
// (2 sub-groups x 4-row unroll). smem sp[k][128] float4: k-stride = 2048 B
// (multiple of 128 B) so each LDS.128 phase hits 32 distinct banks for any
// per-lane k -> conflict-free. Grid 8 x 111 = 888 = 6 CTAs x 148 SMs.
// ---------------------------------------------------------------------------
__global__ __launch_bounds__(BD, 6)
void spline_eval_kernel(const float* __restrict__ X, float* __restrict__ Y) {
    __shared__ float4 sp[NB_IV][CH];     // 30,720 B
    const int t  = threadIdx.x;
    const int c0 = blockIdx.x * CH;

    for (int i = t; i < NB_IV * CH; i += BD)
        ((float4*)sp)[i] = g_poly[(i >> 7) * W_TOTAL + c0 + (i & (CH - 1))];
    __syncthreads();

    const int ch = t & (CH - 1);
    const int rl = t >> 7;               // 0..1
    const int rstep = gridDim.y * 8;

    for (int base = blockIdx.y * 8; base < B_TOTAL; base += rstep) {
        const int r = base + rl * 4;
        const float* xp = X + (size_t)r * W_TOTAL + c0 + ch;
        float*       yp = Y + (size_t)r * W_TOTAL + c0 + ch;

        float xv[4];
#pragma unroll
        for (int q = 0; q < 4; q++) xv[q] = xp[q * W_TOTAL];

        float rv[4];
#pragma unroll
        for (int q = 0; q < 4; q++) {
            float x  = xv[q];
            float fi = floorf(fmaf(x, 2.5f, 7.5f));
            fi       = fminf(fmaxf(fi, 0.0f), 14.0f);
            int   k  = (int)fi;
            float s  = x - fmaf(fi, 0.4f, -3.0f);
            float4 p = sp[k][ch];
            rv[q] = fmaf(fmaf(fmaf(p.w, s, p.z), s, p.y), s, p.x);
        }
#pragma unroll
        for (int q = 0; q < 4; q++) yp[q * W_TOTAL] = rv[q];
    }
}

// ---------------------------------------------------------------------------
extern "C" void kernel_launch(void* const* d_in, const int* in_sizes, int n_in,
                              void* d_out, int out_size) {
    const float* X     = (const float*)d_in[0];
    const float* coefs = (const float*)d_in[1];
    if (n_in >= 2 && in_sizes[0] < in_sizes[1]) {   // identify by size
        X     = (const float*)d_in[1];
        coefs = (const float*)d_in[0];
    }
    float* Y = (float*)d_out;

    build_matrix_kernel<<<1, 64>>>();
    apply_matrix_kernel<<<(NB_IV * W_TOTAL + 255) / 256, 256>>>(coefs);

    dim3 grid(W_TOTAL / CH, 111);        // 8 x 111 = 888 = 6 per SM x 148
    spline_eval_kernel<<<grid, BD>>>(X, Y);
}

// round 4
// speedup vs baseline: 1.2240x; 1.1354x over previous
#include <cuda_runtime.h>

// SplineActivation: y[b,w] = clamped cubic B-spline (16 uniform knots on [-3,3],
// degree 3) of x[b,w], per-channel coefficients coefs[w, 0..17].
//
// Round-4:
//  * Eval kernel unchanged from round 3 (measured ~12.9us: per-(interval,channel)
//    monomial cubic float4 in a 30KB smem tile, 6 CTAs/SM, one exact wave,
//    1 conflict-free LDS.128 + 3-FMA Horner per element).
//  * Build pipeline rebuilt: single FP32 kernel (60 blocks x 256). Threads 0-59
//    of each block redundantly compute the 15x4 interval conversion cubics
//    (FP32 Cox-de Boor sampled at 4 points + divided differences; all
//    denominators >= 0.4 in the clamped span, error ~5e-5 absolute -> ~1e-5
//    rel on y, far under the 1e-3 gate), then each thread emits one g_poly
//    entry. Replaces the 6.9us FP64 kernel + separate apply kernel.

#define W_TOTAL  1024
#define B_TOTAL  8192
#define NB_IV    15
#define CH       128
#define BD       256
#define N_CTRL   18

// Static device scratch (no allocation APIs).
__device__ float4 g_poly[NB_IV * W_TOTAL];   // [interval][channel] monomial cubic

// ---------------------------------------------------------------------------
// Fused build: matrix in smem (FP32), then one table entry per thread.
// Grid 60 x 256 = 15360 = NB_IV * W_TOTAL exactly.
// ---------------------------------------------------------------------------
__global__ __launch_bounds__(BD)
void build_poly_kernel(const float* __restrict__ coefs) {
    __shared__ float4 M[NB_IV * 4];          // [interval][j] -> (b0,b1,b2,b3)
    const int t = threadIdx.x;

    if (t < NB_IV * 4) {
        const int k = t >> 2;                // interval 0..14
        const int j = t & 3;                 // basis index within interval

        // Clamped knot vector (f32 casts of numpy double linspace).
        float tk[22];
#pragma unroll
        for (int m = 0; m < 16; m++)
            tk[3 + m] = (float)(-3.0 + (double)m * (6.0 / 15.0));
        tk[0] = tk[1] = tk[2] = tk[3];
        tk[19] = tk[20] = tk[21] = tk[18];

        const int   kg    = k + 3;
        const float x0    = tk[kg];
        const float delta = (tk[kg + 1] - tk[kg]) * (1.0f / 3.0f);
        const float Kev   = fmaf((float)k, 0.4f, -3.0f);  // eval-kernel origin

        float f[4];
#pragma unroll
        for (int m = 0; m < 4; m++) {
            float x = x0 + delta * (float)m;
            float left[3], right[3];
#pragma unroll
            for (int i2 = 1; i2 <= 3; i2++) {
                left [i2 - 1] = x - tk[kg + 1 - i2];
                right[i2 - 1] = tk[kg + i2] - x;
            }
            float N[4];
            N[0] = 1.0f;
#pragma unroll
            for (int jj = 1; jj <= 3; jj++) {
                float saved = 0.0f;
#pragma unroll
                for (int r = 0; r < jj; r++) {
                    float temp = N[r] / (right[r] + left[jj - 1 - r]);
                    N[r] = saved + right[r] * temp;
                    saved = left[jj - 1 - r] * temp;
                }
                N[jj] = saved;
            }
            f[m] = N[j];                     // unit-coefficient response
        }

        // Uniform divided differences -> monomial cubic in w = x - x0.
        const float id  = 1.0f / delta;
        const float d1  = (f[1] - f[0]) * id;
        const float d2  = (f[2] - 2.0f * f[1] + f[0]) * (0.5f * id * id);
        const float d3  = (f[3] - 3.0f * f[2] + 3.0f * f[1] - f[0])
                          * ((1.0f / 6.0f) * id * id * id);
        const float a0 = f[0];
        const float a1 = d1 - delta * d2 + 2.0f * delta * delta * d3;
        const float a2 = d2 - 3.0f * delta * d3;
        const float a3 = d3;

        // Shift to s = x - Kev (s0 = x0 - Kev is a sub-ulp residual, kept exact).
        const float s0 = x0 - Kev;
        const float b3 = a3;
        const float b2 = a2 - 3.0f * a3 * s0;
        const float b1 = a1 - 2.0f * a2 * s0 + 3.0f * a3 * s0 * s0;
        const float b0 = a0 - a1 * s0 + a2 * s0 * s0 - a3 * s0 * s0 * s0;

        M[t] = make_float4(b0, b1, b2, b3);
    }
    __syncthreads();

    const int idx = blockIdx.x * BD + t;     // 0..15359
    const int c   = idx & (W_TOTAL - 1);
    const int k   = idx >> 10;

    float4 acc = make_float4(0.f, 0.f, 0.f, 0.f);
#pragma unroll
    for (int j = 0; j < 4; j++) {
        float  cf = __ldg(&coefs[c * N_CTRL + k + j]);
        float4 m  = M[k * 4 + j];
        acc.x = fmaf(cf, m.x, acc.x);
        acc.y = fmaf(cf, m.y, acc.y);
        acc.z = fmaf(cf, m.z, acc.z);
        acc.w = fmaf(cf, m.w, acc.w);
    }
    g_poly[k * W_TOTAL + c] = acc;
}

// ---------------------------------------------------------------------------
// Hot kernel (unchanged from round 3). Block = 256 threads over a 128-channel
// tile: ch = t&127, rl = t>>7; 8 rows per block-iteration. smem sp[k][128]
// float4: k-stride = 2048B (multiple of 128B) so every LDS.128 phase hits 32
// distinct banks for any per-lane k. Grid 8 x 111 = 888 = 6 CTAs x 148 SMs.
// ---------------------------------------------------------------------------
__global__ __launch_bounds__(BD, 6)
void spline_eval_kernel(const float* __restrict__ X, float* __restrict__ Y) {
    __shared__ float4 sp[NB_IV][CH];         // 30,720 B
    const int t  = threadIdx.x;
    const int c0 = blockIdx.x * CH;

    for (int i = t; i < NB_IV * CH; i += BD)
        ((float4*)sp)[i] = g_poly[(i >> 7) * W_TOTAL + c0 + (i & (CH - 1))];
    __syncthreads();

    const int ch = t & (CH - 1);
    const int rl = t >> 7;                   // 0..1
    const int rstep = gridDim.y * 8;

    for (int base = blockIdx.y * 8; base < B_TOTAL; base += rstep) {
        const int r = base + rl * 4;
        const float* xp = X + (size_t)r * W_TOTAL + c0 + ch;
        float*       yp = Y + (size_t)r * W_TOTAL + c0 + ch;

        float xv[4];
#pragma unroll
        for (int q = 0; q < 4; q++) xv[q] = xp[q * W_TOTAL];

        float rv[4];
#pragma unroll
        for (int q = 0; q < 4; q++) {
            float x  = xv[q];
            float fi = floorf(fmaf(x, 2.5f, 7.5f));
            fi       = fminf(fmaxf(fi, 0.0f), 14.0f);
            int   k  = (int)fi;
            float s  = x - fmaf(fi, 0.4f, -3.0f);
            float4 p = sp[k][ch];
            rv[q] = fmaf(fmaf(fmaf(p.w, s, p.z), s, p.y), s, p.x);
        }
#pragma unroll
        for (int q = 0; q < 4; q++) yp[q * W_TOTAL] = rv[q];
    }
}

// ---------------------------------------------------------------------------
extern "C" void kernel_launch(void* const* d_in, const int* in_sizes, int n_in,
                              void* d_out, int out_size) {
    const float* X     = (const float*)d_in[0];
    const float* coefs = (const float*)d_in[1];
    if (n_in >= 2 && in_sizes[0] < in_sizes[1]) {   // identify by size
        X     = (const float*)d_in[1];
        coefs = (const float*)d_in[0];
    }
    float* Y = (float*)d_out;

    build_poly_kernel<<<NB_IV * W_TOTAL / BD, BD>>>(coefs);   // 60 x 256

    dim3 grid(W_TOTAL / CH, 111);            // 8 x 111 = 888 = 6 per SM x 148
    spline_eval_kernel<<<grid, BD>>>(X, Y);
}